// round 1
// baseline (speedup 1.0000x reference)
#include <cuda_runtime.h>
#include <cfloat>
#include <math.h>

// ---------------------------------------------------------------------------
// FocalLoss (RetinaNet) fused kernel for GB300.
//   pass 1: zero accumulators
//   pass 2: per-(image, anchor) thread: IoU max/argmax vs GT (shared mem),
//           focal cls sum, smooth-L1 reg sum, block reduce, fp64 atomics
//   pass 3: finalize per-image normalization + batch mean
// ---------------------------------------------------------------------------

#define N_IMG_MAX 32
#define M_MAX 128

__device__ double g_cls_sum[N_IMG_MAX];
__device__ double g_reg_sum[N_IMG_MAX];
__device__ int    g_num_pos[N_IMG_MAX];

__global__ void fl_zero_kernel() {
    int t = threadIdx.x;
    if (t < N_IMG_MAX) {
        g_cls_sum[t] = 0.0;
        g_reg_sum[t] = 0.0;
        g_num_pos[t] = 0;
    }
}

__global__ void fl_main_kernel(const float* __restrict__ cls,
                               const float* __restrict__ reg,
                               const float* __restrict__ anc,
                               const float* __restrict__ ann,
                               int A, int C, int M)
{
    __shared__ float sgx1[M_MAX], sgy1[M_MAX], sgx2[M_MAX], sgy2[M_MAX];
    __shared__ float slbl[M_MAX], sarea[M_MAX];
    __shared__ int   svalid[M_MAX];

    const int b   = blockIdx.y;
    const int tid = threadIdx.x;

    // Load this image's GT boxes into shared memory.
    for (int m = tid; m < M; m += blockDim.x) {
        const float* g = ann + ((size_t)b * M + m) * 5;
        float x1 = g[0], y1 = g[1], x2 = g[2], y2 = g[3], l = g[4];
        sgx1[m] = x1; sgy1[m] = y1; sgx2[m] = x2; sgy2[m] = y2;
        slbl[m] = l;
        sarea[m] = (x2 - x1) * (y2 - y1);
        svalid[m] = (l != -1.0f) ? 1 : 0;
    }
    __syncthreads();

    const int a = blockIdx.x * blockDim.x + tid;

    float cls_acc = 0.0f;
    float reg_acc = 0.0f;
    int   pos_i   = 0;

    if (a < A) {
        const float4 ab = ((const float4*)anc)[a];
        const float aw = ab.z - ab.x;
        const float ah = ab.w - ab.y;
        const float area_a = aw * ah;

        // IoU max / argmax over GT (first-max wins, matching jnp.argmax)
        float best = -FLT_MAX;
        int   arg  = 0;
        #pragma unroll 8
        for (int m = 0; m < M; m++) {
            float iw = fminf(ab.z, sgx2[m]) - fmaxf(ab.x, sgx1[m]);
            float ih = fminf(ab.w, sgy2[m]) - fmaxf(ab.y, sgy1[m]);
            iw = fmaxf(iw, 0.0f);
            ih = fmaxf(ih, 0.0f);
            const float inter = iw * ih;
            const float ua = fmaxf(area_a + sarea[m] - inter, 1e-8f);
            float iou = inter / ua;
            if (!svalid[m]) iou = -1.0f;
            if (iou > best) { best = iou; arg = m; }
        }

        const bool pos = (best >= 0.5f);
        const bool neg = (best <  0.4f);

        if (pos || neg) {
            // Focal classification loss: only pos / neg anchors contribute.
            const int lbl = pos ? (int)slbl[arg] : -1;
            const float* cp = cls + ((size_t)b * A + a) * C;

            float pl[32];
            const int c4 = C >> 2;
            const float4* cp4 = (const float4*)cp;
            #pragma unroll
            for (int i = 0; i < 8; i++) {
                if (i < c4) {
                    float4 v = cp4[i];
                    pl[4*i + 0] = v.x; pl[4*i + 1] = v.y;
                    pl[4*i + 2] = v.z; pl[4*i + 3] = v.w;
                }
            }
            for (int c = c4 * 4; c < C; c++) pl[c] = cp[c];

            float s = 0.0f;
            #pragma unroll 4
            for (int c = 0; c < C; c++) {
                float p = fminf(fmaxf(pl[c], 1e-8f), 1.0f - 1e-8f);
                if (c == lbl) {
                    float q = 1.0f - p;
                    s += 0.2f * q * sqrtf(q) * (-logf(p));
                } else {
                    s += 0.8f * p * sqrtf(p) * (-logf(1.0f - p));
                }
            }
            cls_acc = s;
        }

        if (pos) {
            pos_i = 1;
            const float gx1 = sgx1[arg], gy1 = sgy1[arg];
            const float gx2 = sgx2[arg], gy2 = sgy2[arg];
            const float gwr = gx2 - gx1, ghr = gy2 - gy1;
            const float gcx = gx1 + 0.5f * gwr;
            const float gcy = gy1 + 0.5f * ghr;
            const float gw  = fmaxf(gwr, 1.0f);
            const float gh  = fmaxf(ghr, 1.0f);
            const float acx = ab.x + 0.5f * aw;
            const float acy = ab.y + 0.5f * ah;

            const float t0 = ((gcx - acx) / aw) / 0.1f;
            const float t1 = ((gcy - acy) / ah) / 0.1f;
            const float t2 = logf(gw / aw) / 0.2f;
            const float t3 = logf(gh / ah) / 0.2f;

            const float4 rg = ((const float4*)reg)[(size_t)b * A + a];

            const float thr = 1.0f / 9.0f;
            const float off = 0.5f / 9.0f;
            float s = 0.0f;
            float d;
            d = fabsf(t0 - rg.x); s += (d <= thr) ? 4.5f * d * d : d - off;
            d = fabsf(t1 - rg.y); s += (d <= thr) ? 4.5f * d * d : d - off;
            d = fabsf(t2 - rg.z); s += (d <= thr) ? 4.5f * d * d : d - off;
            d = fabsf(t3 - rg.w); s += (d <= thr) ? 4.5f * d * d : d - off;
            reg_acc = s;
        }
    }

    // ---- block reduction (warp shuffle, then shared, then fp64 atomic) ----
    const unsigned FULL = 0xFFFFFFFFu;
    #pragma unroll
    for (int o = 16; o > 0; o >>= 1) {
        cls_acc += __shfl_down_sync(FULL, cls_acc, o);
        reg_acc += __shfl_down_sync(FULL, reg_acc, o);
        pos_i   += __shfl_down_sync(FULL, pos_i,   o);
    }

    __shared__ float wc[8], wr[8];
    __shared__ int   wp[8];
    const int wid = tid >> 5;
    const int lid = tid & 31;
    if (lid == 0) { wc[wid] = cls_acc; wr[wid] = reg_acc; wp[wid] = pos_i; }
    __syncthreads();

    if (wid == 0) {
        const int nwarp = blockDim.x >> 5;
        float c = (lid < nwarp) ? wc[lid] : 0.0f;
        float r = (lid < nwarp) ? wr[lid] : 0.0f;
        int   p = (lid < nwarp) ? wp[lid] : 0;
        #pragma unroll
        for (int o = 4; o > 0; o >>= 1) {
            c += __shfl_down_sync(FULL, c, o);
            r += __shfl_down_sync(FULL, r, o);
            p += __shfl_down_sync(FULL, p, o);
        }
        if (lid == 0) {
            if (c != 0.0f) atomicAdd(&g_cls_sum[b], (double)c);
            if (r != 0.0f) atomicAdd(&g_reg_sum[b], (double)r);
            if (p != 0)    atomicAdd(&g_num_pos[b], p);
        }
    }
}

__global__ void fl_finalize_kernel(const float* __restrict__ ann,
                                   float* __restrict__ out,
                                   int B, int M)
{
    if (threadIdx.x == 0 && blockIdx.x == 0) {
        float cl = 0.0f, rl = 0.0f;
        for (int b = 0; b < B; b++) {
            int nv = 0;
            for (int m = 0; m < M; m++)
                nv += (ann[((size_t)b * M + m) * 5 + 4] != -1.0f) ? 1 : 0;
            const int np = g_num_pos[b];
            const float npf = (float)np;
            float c = (float)g_cls_sum[b] / fmaxf(npf, 1.0f);
            float r = (float)g_reg_sum[b] / fmaxf(4.0f * npf, 1.0f);
            if (np == 0) r = 0.0f;
            if (nv == 0) { c = 0.0f; r = 0.0f; }
            cl += c;
            rl += r;
        }
        out[0] = cl / (float)B;
        out[1] = rl / (float)B;
    }
}

extern "C" void kernel_launch(void* const* d_in, const int* in_sizes, int n_in,
                              void* d_out, int out_size)
{
    const float* cls = (const float*)d_in[0];
    const float* reg = (const float*)d_in[1];
    const float* anc = (const float*)d_in[2];
    const float* ann = (const float*)d_in[3];
    float* out = (float*)d_out;

    const int A = in_sizes[2] / 4;            // anchors [1,A,4]
    const int B = in_sizes[1] / (A * 4);      // regressions [B,A,4]
    const int C = in_sizes[0] / (B * A);      // classifications [B,A,C]
    const int M = in_sizes[3] / (B * 5);      // annotations [B,M,5]

    fl_zero_kernel<<<1, 32>>>();

    dim3 block(256);
    dim3 grid((A + 255) / 256, B);
    fl_main_kernel<<<grid, block>>>(cls, reg, anc, ann, A, C, M);

    fl_finalize_kernel<<<1, 32>>>(ann, out, B, M);
}

// round 2
// speedup vs baseline: 2.4874x; 2.4874x over previous
#include <cuda_runtime.h>
#include <cfloat>
#include <math.h>

// ---------------------------------------------------------------------------
// FocalLoss (RetinaNet) fused kernel for GB300, v2.
//   kernel 1: per-(image, anchor) thread:
//             - division-free IoU max/argmax vs GT (float4 smem, cross-mult)
//             - branch-free focal cls sum (fast MUFU transcendentals),
//               divergent fixup for the rare positive anchors
//             - smooth-L1 reg sum for positives
//             - block reduce -> per-block partials (no atomics, no zero pass)
//   kernel 2: finalize per-image normalization + batch mean
// ---------------------------------------------------------------------------

#define TPB 256
#define M_MAX 64
#define MAXB 32768

__device__ float g_pc[MAXB];   // per-block cls partial
__device__ float g_pr[MAXB];   // per-block reg partial
__device__ int   g_pp[MAXB];   // per-block num_pos partial

template <int MT, int CT>
__global__ void fl_main_kernel(const float* __restrict__ cls,
                               const float* __restrict__ reg,
                               const float* __restrict__ anc,
                               const float* __restrict__ ann,
                               int A, int C, int M)
{
    __shared__ float4 sbox[M_MAX];
    __shared__ float  sarea[M_MAX];
    __shared__ float  slbl[M_MAX];

    const int b   = blockIdx.y;
    const int tid = threadIdx.x;
    const int MM  = MT ? MT : M;

    for (int m = tid; m < MM; m += TPB) {
        const float* g = ann + ((size_t)b * MM + m) * 5;
        float x1 = g[0], y1 = g[1], x2 = g[2], y2 = g[3], l = g[4];
        if (l == -1.0f) { x1 = 0.f; y1 = 0.f; x2 = 0.f; y2 = 0.f; }
        sbox[m]  = make_float4(x1, y1, x2, y2);
        sarea[m] = (x2 - x1) * (y2 - y1);
        slbl[m]  = l;
    }
    __syncthreads();

    const int a = blockIdx.x * TPB + tid;

    float cls_acc = 0.0f;
    float reg_acc = 0.0f;
    int   pos_i   = 0;

    if (a < A) {
        const float4 ab = ((const float4*)anc)[a];
        const float aw = ab.z - ab.x;
        const float ah = ab.w - ab.y;
        const float area_a = aw * ah;

        // Prefetch classification row (hides DRAM latency under the IoU loop).
        float4 c0, c1, c2, c3, c4;
        const float* cp = cls + ((size_t)b * A + a) * (CT ? CT : C);
        if (CT == 20) {
            const float4* cp4 = (const float4*)cp;
            c0 = cp4[0]; c1 = cp4[1]; c2 = cp4[2]; c3 = cp4[3]; c4 = cp4[4];
        }

        // --- IoU max/argmax, division-free (cross-multiplied compare) ---
        // invalid GTs are degenerate (0,0,0,0) -> inter=0 -> iou=0; this can
        // never reach the 0.5 positive threshold, and arg is only consumed
        // for positive anchors, so this is equivalent to the reference's -1.
        float binter = 0.0f;
        float bua    = 1.0f;
        int   arg    = 0;
        #pragma unroll
        for (int m = 0; m < MM; m++) {
            const float4 g = sbox[m];
            float iw = fminf(ab.z, g.z) - fmaxf(ab.x, g.x);
            float ih = fminf(ab.w, g.w) - fmaxf(ab.y, g.y);
            const float inter = fmaxf(iw, 0.0f) * fmaxf(ih, 0.0f);
            const float ua = area_a + sarea[m] - inter;   // >= area_a >= 256 >> eps
            if (inter * bua > binter * ua) {
                binter = inter; bua = ua; arg = m;
            }
        }
        const float best = binter / bua;      // one precise division
        const bool  pos  = (best >= 0.5f);

        if (pos || best < 0.4f) {
            // Branch-free negative focal term for all classes:
            //   s += p^1.5 * log(1-p)   (negative); cls_acc = -0.8 * s
            float s = 0.0f;
            if (CT == 20) {
                const float pv[20] = {c0.x,c0.y,c0.z,c0.w, c1.x,c1.y,c1.z,c1.w,
                                      c2.x,c2.y,c2.z,c2.w, c3.x,c3.y,c3.z,c3.w,
                                      c4.x,c4.y,c4.z,c4.w};
                #pragma unroll
                for (int c = 0; c < 20; c++) {
                    const float p = pv[c];
                    const float p15 = p * p * rsqrtf(p);      // p^1.5
                    s = fmaf(p15, __logf(1.0f - p), s);
                }
            } else {
                for (int c = 0; c < C; c++) {
                    const float p = fminf(fmaxf(cp[c], 1e-8f), 1.0f - 1e-8f);
                    const float p15 = p * p * rsqrtf(p);
                    s = fmaf(p15, __logf(1.0f - p), s);
                }
            }
            cls_acc = -0.8f * s;

            if (pos) {
                pos_i = 1;
                const int lbl = (int)slbl[arg];
                const float pl = cp[lbl];                 // L1-hot reload
                const float ql = 1.0f - pl;
                const float fneg = pl * pl * rsqrtf(pl) * (-__logf(ql));
                const float fpos = ql * ql * rsqrtf(ql) * (-__logf(pl));
                cls_acc += 0.2f * fpos - 0.8f * fneg;

                // --- smooth-L1 regression loss ---
                const float4 gb = sbox[arg];
                const float gwr = gb.z - gb.x, ghr = gb.w - gb.y;
                const float gcx = gb.x + 0.5f * gwr;
                const float gcy = gb.y + 0.5f * ghr;
                const float gw  = fmaxf(gwr, 1.0f);
                const float gh  = fmaxf(ghr, 1.0f);
                const float acx = ab.x + 0.5f * aw;
                const float acy = ab.y + 0.5f * ah;

                const float t0 = ((gcx - acx) / aw) / 0.1f;
                const float t1 = ((gcy - acy) / ah) / 0.1f;
                const float t2 = logf(gw / aw) / 0.2f;
                const float t3 = logf(gh / ah) / 0.2f;

                const float4 rg = ((const float4*)reg)[(size_t)b * A + a];

                const float thr = 1.0f / 9.0f;
                const float off = 0.5f / 9.0f;
                float sr = 0.0f, d;
                d = fabsf(t0 - rg.x); sr += (d <= thr) ? 4.5f * d * d : d - off;
                d = fabsf(t1 - rg.y); sr += (d <= thr) ? 4.5f * d * d : d - off;
                d = fabsf(t2 - rg.z); sr += (d <= thr) ? 4.5f * d * d : d - off;
                d = fabsf(t3 - rg.w); sr += (d <= thr) ? 4.5f * d * d : d - off;
                reg_acc = sr;
            }
        }
    }

    // ---- block reduction: warp shuffle -> shared -> per-block partial ----
    const unsigned FULL = 0xFFFFFFFFu;
    #pragma unroll
    for (int o = 16; o > 0; o >>= 1) {
        cls_acc += __shfl_down_sync(FULL, cls_acc, o);
        reg_acc += __shfl_down_sync(FULL, reg_acc, o);
        pos_i   += __shfl_down_sync(FULL, pos_i,   o);
    }

    __shared__ float wc[TPB / 32], wr[TPB / 32];
    __shared__ int   wp[TPB / 32];
    const int wid = tid >> 5;
    const int lid = tid & 31;
    if (lid == 0) { wc[wid] = cls_acc; wr[wid] = reg_acc; wp[wid] = pos_i; }
    __syncthreads();

    if (wid == 0) {
        const int nwarp = TPB / 32;
        float csum = (lid < nwarp) ? wc[lid] : 0.0f;
        float rsum = (lid < nwarp) ? wr[lid] : 0.0f;
        int   psum = (lid < nwarp) ? wp[lid] : 0;
        #pragma unroll
        for (int o = 4; o > 0; o >>= 1) {
            csum += __shfl_down_sync(FULL, csum, o);
            rsum += __shfl_down_sync(FULL, rsum, o);
            psum += __shfl_down_sync(FULL, psum, o);
        }
        if (lid == 0) {
            const int bid = blockIdx.y * gridDim.x + blockIdx.x;
            g_pc[bid] = csum;
            g_pr[bid] = rsum;
            g_pp[bid] = psum;
        }
    }
}

__global__ void fl_finalize_kernel(const float* __restrict__ ann,
                                   float* __restrict__ out,
                                   int B, int M, int NBX)
{
    const int w   = threadIdx.x >> 5;
    const int lid = threadIdx.x & 31;
    __shared__ float scl[32], srl[32];
    const unsigned FULL = 0xFFFFFFFFu;

    if (w < B) {
        double c = 0.0, r = 0.0;
        int p = 0;
        for (int i = lid; i < NBX; i += 32) {
            const int idx = w * NBX + i;
            c += (double)g_pc[idx];
            r += (double)g_pr[idx];
            p += g_pp[idx];
        }
        #pragma unroll
        for (int o = 16; o > 0; o >>= 1) {
            c += __shfl_down_sync(FULL, c, o);
            r += __shfl_down_sync(FULL, r, o);
            p += __shfl_down_sync(FULL, p, o);
        }
        if (lid == 0) {
            int nv = 0;
            for (int m = 0; m < M; m++)
                nv += (ann[((size_t)w * M + m) * 5 + 4] != -1.0f) ? 1 : 0;
            const float npf = (float)p;
            float cl = (float)c / fmaxf(npf, 1.0f);
            float rl = (float)r / fmaxf(4.0f * npf, 1.0f);
            if (p == 0) rl = 0.0f;
            if (nv == 0) { cl = 0.0f; rl = 0.0f; }
            scl[w] = cl;
            srl[w] = rl;
        }
    }
    __syncthreads();

    if (threadIdx.x == 0) {
        float cl = 0.0f, rl = 0.0f;
        for (int b = 0; b < B; b++) { cl += scl[b]; rl += srl[b]; }
        out[0] = cl / (float)B;
        out[1] = rl / (float)B;
    }
}

extern "C" void kernel_launch(void* const* d_in, const int* in_sizes, int n_in,
                              void* d_out, int out_size)
{
    const float* cls = (const float*)d_in[0];
    const float* reg = (const float*)d_in[1];
    const float* anc = (const float*)d_in[2];
    const float* ann = (const float*)d_in[3];
    float* out = (float*)d_out;

    const int A = in_sizes[2] / 4;            // anchors [1,A,4]
    const int B = in_sizes[1] / (A * 4);      // regressions [B,A,4]
    const int C = in_sizes[0] / (B * A);      // classifications [B,A,C]
    const int M = in_sizes[3] / (B * 5);      // annotations [B,M,5]

    dim3 block(TPB);
    dim3 grid((A + TPB - 1) / TPB, B);

    if (M == 32 && C == 20)
        fl_main_kernel<32, 20><<<grid, block>>>(cls, reg, anc, ann, A, C, M);
    else
        fl_main_kernel<0, 0><<<grid, block>>>(cls, reg, anc, ann, A, C, M);

    fl_finalize_kernel<<<1, 256>>>(ann, out, B, M, grid.x);
}

// round 3
// speedup vs baseline: 2.6063x; 1.0478x over previous
#include <cuda_runtime.h>
#include <cfloat>
#include <math.h>

// ---------------------------------------------------------------------------
// FocalLoss (RetinaNet) fully-fused single-kernel version for GB300, v3.
//   - warp-ballot compaction of valid GT boxes (32 -> ~28 IoU iterations)
//   - division-free IoU argmax (cross-multiplied compare), one precise
//     division per anchor for the 0.4/0.5 thresholds
//   - branch-free focal cls sum with fast MUFU transcendentals
//   - block reduce -> fp64 atomics into per-image accumulators
//   - last-block-done pattern finalizes output and resets accumulators
//     (deterministic: every call does identical work, state returns to 0)
// ---------------------------------------------------------------------------

#define TPB 256
#define M_MAX 64
#define B_MAX 32

__device__ double g_cs[B_MAX];   // per-image cls sum      (zero-init, reset by last block)
__device__ double g_rs[B_MAX];   // per-image reg sum
__device__ int    g_np[B_MAX];   // per-image num_pos
__device__ int    g_arrive = 0;  // arrival counter

template <int MT, int CT>
__global__ void __launch_bounds__(TPB)
fl_kernel(const float* __restrict__ cls,
          const float* __restrict__ reg,
          const float* __restrict__ anc,
          const float* __restrict__ ann,
          float* __restrict__ out,
          int A, int C, int M, int B, int nblocks)
{
    __shared__ float4 sbox[M_MAX];
    __shared__ float  sarea[M_MAX];
    __shared__ int    slbl[M_MAX];
    __shared__ int    s_nv;
    __shared__ bool   s_last;

    const int b   = blockIdx.y;
    const int tid = threadIdx.x;
    const unsigned FULL = 0xFFFFFFFFu;

    // ---- load + compact valid GT boxes ----
    if (MT == 32) {
        if (tid < 32) {
            const float* g = ann + ((size_t)b * 32 + tid) * 5;
            const float x1 = g[0], y1 = g[1], x2 = g[2], y2 = g[3], l = g[4];
            const bool v = (l != -1.0f);
            const unsigned mask = __ballot_sync(FULL, v);
            if (v) {
                const int p = __popc(mask & ((1u << tid) - 1u));
                sbox[p]  = make_float4(x1, y1, x2, y2);
                sarea[p] = (x2 - x1) * (y2 - y1);
                slbl[p]  = (int)l;
            }
            if (tid == 0) s_nv = __popc(mask);
        }
    } else {
        if (tid == 0) {
            int p = 0;
            for (int m = 0; m < M; m++) {
                const float* g = ann + ((size_t)b * M + m) * 5;
                const float l = g[4];
                if (l != -1.0f) {
                    sbox[p]  = make_float4(g[0], g[1], g[2], g[3]);
                    sarea[p] = (g[2] - g[0]) * (g[3] - g[1]);
                    slbl[p]  = (int)l;
                    p++;
                }
            }
            s_nv = p;
        }
    }
    __syncthreads();
    const int nv = s_nv;

    const int a = blockIdx.x * TPB + tid;

    float cls_acc = 0.0f;
    float reg_acc = 0.0f;
    int   pos_i   = 0;

    if (a < A) {
        const float4 ab = ((const float4*)anc)[a];
        const float aw = ab.z - ab.x;
        const float ah = ab.w - ab.y;
        const float area_a = aw * ah;

        // Prefetch classification row (hides DRAM latency under the IoU loop).
        float4 c0, c1, c2, c3, c4;
        const float* cp = cls + ((size_t)b * A + a) * (CT ? CT : C);
        if (CT == 20) {
            const float4* cp4 = (const float4*)cp;
            c0 = cp4[0]; c1 = cp4[1]; c2 = cp4[2]; c3 = cp4[3]; c4 = cp4[4];
        }

        // --- IoU max/argmax over valid GTs, division-free compare ---
        float binter = 0.0f;   // iou = 0 if nv == 0 -> negative anchor;
        float bua    = 1.0f;   // finalize zeroes the whole image if nv == 0.
        int   arg    = 0;
        #pragma unroll 4
        for (int m = 0; m < nv; m++) {
            const float4 g = sbox[m];
            const float iw = fminf(ab.z, g.z) - fmaxf(ab.x, g.x);
            const float ih = fminf(ab.w, g.w) - fmaxf(ab.y, g.y);
            const float inter = fmaxf(iw, 0.0f) * fmaxf(ih, 0.0f);
            const float ua = area_a + sarea[m] - inter;  // >= area_a >= 256
            if (inter * bua > binter * ua) {
                binter = inter; bua = ua; arg = m;
            }
        }
        const float best = binter / bua;     // one precise division
        const bool  pos  = (best >= 0.5f);

        if (pos || best < 0.4f) {
            // Branch-free negative focal term for all classes.
            float s = 0.0f;
            if (CT == 20) {
                const float pv[20] = {c0.x,c0.y,c0.z,c0.w, c1.x,c1.y,c1.z,c1.w,
                                      c2.x,c2.y,c2.z,c2.w, c3.x,c3.y,c3.z,c3.w,
                                      c4.x,c4.y,c4.z,c4.w};
                #pragma unroll
                for (int c = 0; c < 20; c++) {
                    const float p = pv[c];
                    const float p15 = p * p * rsqrtf(p);     // p^1.5
                    s = fmaf(p15, __logf(1.0f - p), s);
                }
            } else {
                for (int c = 0; c < C; c++) {
                    const float p = fminf(fmaxf(cp[c], 1e-8f), 1.0f - 1e-8f);
                    const float p15 = p * p * rsqrtf(p);
                    s = fmaf(p15, __logf(1.0f - p), s);
                }
            }
            cls_acc = -0.8f * s;

            if (pos) {
                pos_i = 1;
                const int lbl = slbl[arg];
                const float pl = cp[lbl];                // L1-hot reload
                const float ql = 1.0f - pl;
                const float fneg = pl * pl * rsqrtf(pl) * (-__logf(ql));
                const float fpos = ql * ql * rsqrtf(ql) * (-__logf(pl));
                cls_acc += 0.2f * fpos - 0.8f * fneg;

                // --- smooth-L1 regression loss ---
                const float4 gb = sbox[arg];
                const float gwr = gb.z - gb.x, ghr = gb.w - gb.y;
                const float gcx = gb.x + 0.5f * gwr;
                const float gcy = gb.y + 0.5f * ghr;
                const float gw  = fmaxf(gwr, 1.0f);
                const float gh  = fmaxf(ghr, 1.0f);
                const float acx = ab.x + 0.5f * aw;
                const float acy = ab.y + 0.5f * ah;

                const float t0 = ((gcx - acx) / aw) / 0.1f;
                const float t1 = ((gcy - acy) / ah) / 0.1f;
                const float t2 = logf(gw / aw) / 0.2f;
                const float t3 = logf(gh / ah) / 0.2f;

                const float4 rg = ((const float4*)reg)[(size_t)b * A + a];

                const float thr = 1.0f / 9.0f;
                const float off = 0.5f / 9.0f;
                float sr = 0.0f, d;
                d = fabsf(t0 - rg.x); sr += (d <= thr) ? 4.5f * d * d : d - off;
                d = fabsf(t1 - rg.y); sr += (d <= thr) ? 4.5f * d * d : d - off;
                d = fabsf(t2 - rg.z); sr += (d <= thr) ? 4.5f * d * d : d - off;
                d = fabsf(t3 - rg.w); sr += (d <= thr) ? 4.5f * d * d : d - off;
                reg_acc = sr;
            }
        }
    }

    // ---- block reduction: warp shuffle -> shared -> fp64 atomics ----
    #pragma unroll
    for (int o = 16; o > 0; o >>= 1) {
        cls_acc += __shfl_down_sync(FULL, cls_acc, o);
        reg_acc += __shfl_down_sync(FULL, reg_acc, o);
        pos_i   += __shfl_down_sync(FULL, pos_i,   o);
    }

    __shared__ float wc[TPB / 32], wr[TPB / 32];
    __shared__ int   wp[TPB / 32];
    const int wid = tid >> 5;
    const int lid = tid & 31;
    if (lid == 0) { wc[wid] = cls_acc; wr[wid] = reg_acc; wp[wid] = pos_i; }
    __syncthreads();

    if (tid < 32) {
        const int nwarp = TPB / 32;
        float csum = (lid < nwarp) ? wc[lid] : 0.0f;
        float rsum = (lid < nwarp) ? wr[lid] : 0.0f;
        int   psum = (lid < nwarp) ? wp[lid] : 0;
        #pragma unroll
        for (int o = 4; o > 0; o >>= 1) {
            csum += __shfl_down_sync(FULL, csum, o);
            rsum += __shfl_down_sync(FULL, rsum, o);
            psum += __shfl_down_sync(FULL, psum, o);
        }
        if (lid == 0) {
            if (csum != 0.0f) atomicAdd(&g_cs[b], (double)csum);
            if (rsum != 0.0f) atomicAdd(&g_rs[b], (double)rsum);
            if (psum != 0)    atomicAdd(&g_np[b], psum);
            __threadfence();
            const int prev = atomicAdd(&g_arrive, 1);
            s_last = (prev == nblocks - 1);
        }
    }
    __syncthreads();

    // ---- last block finalizes the output and resets the accumulators ----
    if (s_last && tid < 32) {
        float cl = 0.0f, rl = 0.0f;
        if (tid < B) {
            int nvv = 0;
            for (int m = 0; m < M; m++)
                nvv += (ann[((size_t)tid * M + m) * 5 + 4] != -1.0f) ? 1 : 0;
            const int np = g_np[tid];
            const float npf = (float)np;
            cl = (float)g_cs[tid] / fmaxf(npf, 1.0f);
            rl = (float)g_rs[tid] / fmaxf(4.0f * npf, 1.0f);
            if (np == 0) rl = 0.0f;
            if (nvv == 0) { cl = 0.0f; rl = 0.0f; }
        }
        #pragma unroll
        for (int o = 16; o > 0; o >>= 1) {
            cl += __shfl_down_sync(FULL, cl, o);
            rl += __shfl_down_sync(FULL, rl, o);
        }
        if (tid == 0) {
            out[0] = cl / (float)B;
            out[1] = rl / (float)B;
        }
        // reset state for the next (identical) call
        g_cs[tid] = 0.0;
        g_rs[tid] = 0.0;
        g_np[tid] = 0;
        if (tid == 0) g_arrive = 0;
    }
}

extern "C" void kernel_launch(void* const* d_in, const int* in_sizes, int n_in,
                              void* d_out, int out_size)
{
    const float* cls = (const float*)d_in[0];
    const float* reg = (const float*)d_in[1];
    const float* anc = (const float*)d_in[2];
    const float* ann = (const float*)d_in[3];
    float* out = (float*)d_out;

    const int A = in_sizes[2] / 4;            // anchors [1,A,4]
    const int B = in_sizes[1] / (A * 4);      // regressions [B,A,4]
    const int C = in_sizes[0] / (B * A);      // classifications [B,A,C]
    const int M = in_sizes[3] / (B * 5);      // annotations [B,M,5]

    dim3 block(TPB);
    dim3 grid((A + TPB - 1) / TPB, B);
    const int nblocks = grid.x * grid.y;

    if (M == 32 && C == 20)
        fl_kernel<32, 20><<<grid, block>>>(cls, reg, anc, ann, out, A, C, M, B, nblocks);
    else
        fl_kernel<0, 0><<<grid, block>>>(cls, reg, anc, ann, out, A, C, M, B, nblocks);
}

// round 5
// speedup vs baseline: 2.7351x; 1.0494x over previous
#include <cuda_runtime.h>
#include <cfloat>
#include <stdint.h>
#include <math.h>

// ---------------------------------------------------------------------------
// FocalLoss (RetinaNet) fully-fused single-kernel for GB300, v5.
//   - fully-unrolled 32-iteration IoU loop (invalid GT -> degenerate box,
//     provably never argmax-selected; compile-time bound => ptxas batches
//     the LDS and schedules the FMNMX chain without loop overhead)
//   - division-free argmax via inter_i*S_j > inter_j*S_i (ua terms cancel)
//   - one precise division per anchor for the exact 0.4/0.5 thresholds
//   - branch-free focal cls sum with fast MUFU transcendentals
//   - last-block-done finalize + accumulator reset (single launch)
// ---------------------------------------------------------------------------

#define TPB 256
#define M_MAX 64
#define B_MAX 32

__device__ double g_cs[B_MAX];
__device__ double g_rs[B_MAX];
__device__ int    g_np[B_MAX];
__device__ int    g_arrive = 0;

template <int MT, int CT>
__global__ void __launch_bounds__(TPB, 5)
fl_kernel(const float* __restrict__ cls,
          const float* __restrict__ reg,
          const float* __restrict__ anc,
          const float* __restrict__ ann,
          float* __restrict__ out,
          int A, int C, int M, int B, int nblocks)
{
    __shared__ float4 sbox[M_MAX];   // (x1, y1, x2, y2)
    __shared__ float  sarea[M_MAX];
    __shared__ int    slbl[M_MAX];
    __shared__ bool   s_last;

    const int b   = blockIdx.y;
    const int tid = threadIdx.x;
    const int MM  = MT ? MT : M;
    const unsigned FULL = 0xFFFFFFFFu;

    // ---- load GT boxes (invalid -> degenerate zero box, never selected) ----
    if (tid < MM) {
        const float* g = ann + ((size_t)b * MM + tid) * 5;
        float x1 = g[0], y1 = g[1], x2 = g[2], y2 = g[3];
        const float l = g[4];
        if (l == -1.0f) { x1 = 0.f; y1 = 0.f; x2 = 0.f; y2 = 0.f; }
        sbox[tid]  = make_float4(x1, y1, x2, y2);
        sarea[tid] = (x2 - x1) * (y2 - y1);
        slbl[tid]  = (int)l;
    }
    __syncthreads();

    const int a = blockIdx.x * TPB + tid;

    float cls_acc = 0.0f;
    float reg_acc = 0.0f;
    int   pos_i   = 0;

    if (a < A) {
        const float4 ab = ((const float4*)anc)[a];
        const float aw = ab.z - ab.x;
        const float ah = ab.w - ab.y;
        const float area_a = aw * ah;

        // Prefetch classification row (hides DRAM latency under the IoU loop).
        float4 c0, c1, c2, c3, c4;
        const float* cp = cls + ((size_t)b * A + a) * (CT ? CT : C);
        if (CT == 20) {
            const float4* cp4 = (const float4*)cp;
            c0 = cp4[0]; c1 = cp4[1]; c2 = cp4[2]; c3 = cp4[3]; c4 = cp4[4];
        }

        // --- IoU max/argmax, cancelled cross-multiply compare ---
        // iou_m = inter_m / (S_m - inter_m), S_m = area_a + area_b[m]
        // iou_i > iou_j  <=>  inter_i*S_j > inter_j*S_i
        float binter = 0.0f;
        float bS     = 1.0f;
        int   arg    = 0;
        #pragma unroll
        for (int m = 0; m < MM; m++) {
            const float4 g = sbox[m];
            const float iw = fminf(ab.z, g.z) - fmaxf(ab.x, g.x);
            const float ih = fminf(ab.w, g.w) - fmaxf(ab.y, g.y);
            const float inter = fmaxf(iw, 0.0f) * fmaxf(ih, 0.0f);
            const float S = area_a + sarea[m];
            if (inter * bS > binter * S) {
                binter = inter; bS = S; arg = m;
            }
        }
        const float best = binter / (bS - binter);    // one precise division
        const bool  pos  = (best >= 0.5f);

        if (pos || best < 0.4f) {
            // Branch-free negative focal term for all classes.
            float s = 0.0f;
            if (CT == 20) {
                const float pv[20] = {c0.x,c0.y,c0.z,c0.w, c1.x,c1.y,c1.z,c1.w,
                                      c2.x,c2.y,c2.z,c2.w, c3.x,c3.y,c3.z,c3.w,
                                      c4.x,c4.y,c4.z,c4.w};
                #pragma unroll
                for (int c = 0; c < 20; c++) {
                    const float p = pv[c];
                    const float p15 = p * p * rsqrtf(p);     // p^1.5
                    s = fmaf(p15, __logf(1.0f - p), s);
                }
            } else {
                for (int c = 0; c < C; c++) {
                    const float p = fminf(fmaxf(cp[c], 1e-8f), 1.0f - 1e-8f);
                    const float p15 = p * p * rsqrtf(p);
                    s = fmaf(p15, __logf(1.0f - p), s);
                }
            }
            cls_acc = -0.8f * s;

            if (pos) {
                pos_i = 1;
                const int lbl = slbl[arg];
                const float pl = cp[lbl];                    // L1/L2-hot reload
                const float ql = 1.0f - pl;
                const float fneg = pl * pl * rsqrtf(pl) * (-__logf(ql));
                const float fpos = ql * ql * rsqrtf(ql) * (-__logf(pl));
                cls_acc += 0.2f * fpos - 0.8f * fneg;

                // --- smooth-L1 regression loss ---
                const float4 gb = sbox[arg];
                const float gwr = gb.z - gb.x, ghr = gb.w - gb.y;
                const float gcx = gb.x + 0.5f * gwr;
                const float gcy = gb.y + 0.5f * ghr;
                const float gw  = fmaxf(gwr, 1.0f);
                const float gh  = fmaxf(ghr, 1.0f);
                const float acx = ab.x + 0.5f * aw;
                const float acy = ab.y + 0.5f * ah;

                const float t0 = ((gcx - acx) / aw) / 0.1f;
                const float t1 = ((gcy - acy) / ah) / 0.1f;
                const float t2 = logf(gw / aw) / 0.2f;
                const float t3 = logf(gh / ah) / 0.2f;

                const float4 rg = ((const float4*)reg)[(size_t)b * A + a];

                const float thr = 1.0f / 9.0f;
                const float off = 0.5f / 9.0f;
                float sr = 0.0f, d;
                d = fabsf(t0 - rg.x); sr += (d <= thr) ? 4.5f * d * d : d - off;
                d = fabsf(t1 - rg.y); sr += (d <= thr) ? 4.5f * d * d : d - off;
                d = fabsf(t2 - rg.z); sr += (d <= thr) ? 4.5f * d * d : d - off;
                d = fabsf(t3 - rg.w); sr += (d <= thr) ? 4.5f * d * d : d - off;
                reg_acc = sr;
            }
        }
    }

    // ---- block reduction: warp shuffle -> shared -> fp64 atomics ----
    #pragma unroll
    for (int o = 16; o > 0; o >>= 1) {
        cls_acc += __shfl_down_sync(FULL, cls_acc, o);
        reg_acc += __shfl_down_sync(FULL, reg_acc, o);
        pos_i   += __shfl_down_sync(FULL, pos_i,   o);
    }

    __shared__ float wc[TPB / 32], wr[TPB / 32];
    __shared__ int   wp[TPB / 32];
    const int wid = tid >> 5;
    const int lid = tid & 31;
    if (lid == 0) { wc[wid] = cls_acc; wr[wid] = reg_acc; wp[wid] = pos_i; }
    __syncthreads();

    if (tid < 32) {
        const int nwarp = TPB / 32;
        float csum = (lid < nwarp) ? wc[lid] : 0.0f;
        float rsum = (lid < nwarp) ? wr[lid] : 0.0f;
        int   psum = (lid < nwarp) ? wp[lid] : 0;
        #pragma unroll
        for (int o = 4; o > 0; o >>= 1) {
            csum += __shfl_down_sync(FULL, csum, o);
            rsum += __shfl_down_sync(FULL, rsum, o);
            psum += __shfl_down_sync(FULL, psum, o);
        }
        if (lid == 0) {
            if (csum != 0.0f) atomicAdd(&g_cs[b], (double)csum);
            if (rsum != 0.0f) atomicAdd(&g_rs[b], (double)rsum);
            if (psum != 0)    atomicAdd(&g_np[b], psum);
            __threadfence();
            const int prev = atomicAdd(&g_arrive, 1);
            s_last = (prev == nblocks - 1);
        }
    }
    __syncthreads();

    // ---- last block finalizes the output and resets the accumulators ----
    if (s_last && tid < 32) {
        float cl = 0.0f, rl = 0.0f;
        if (tid < B) {
            int nvv = 0;
            for (int m = 0; m < M; m++)
                nvv += (ann[((size_t)tid * M + m) * 5 + 4] != -1.0f) ? 1 : 0;
            const int np = g_np[tid];
            const float npf = (float)np;
            cl = (float)g_cs[tid] / fmaxf(npf, 1.0f);
            rl = (float)g_rs[tid] / fmaxf(4.0f * npf, 1.0f);
            if (np == 0) rl = 0.0f;
            if (nvv == 0) { cl = 0.0f; rl = 0.0f; }
        }
        #pragma unroll
        for (int o = 16; o > 0; o >>= 1) {
            cl += __shfl_down_sync(FULL, cl, o);
            rl += __shfl_down_sync(FULL, rl, o);
        }
        if (tid == 0) {
            out[0] = cl / (float)B;
            out[1] = rl / (float)B;
        }
        g_cs[tid] = 0.0;
        g_rs[tid] = 0.0;
        g_np[tid] = 0;
        if (tid == 0) g_arrive = 0;
    }
}

extern "C" void kernel_launch(void* const* d_in, const int* in_sizes, int n_in,
                              void* d_out, int out_size)
{
    const float* cls = (const float*)d_in[0];
    const float* reg = (const float*)d_in[1];
    const float* anc = (const float*)d_in[2];
    const float* ann = (const float*)d_in[3];
    float* out = (float*)d_out;

    const int A = in_sizes[2] / 4;            // anchors [1,A,4]
    const int B = in_sizes[1] / (A * 4);      // regressions [B,A,4]
    const int C = in_sizes[0] / (B * A);      // classifications [B,A,C]
    const int M = in_sizes[3] / (B * 5);      // annotations [B,M,5]

    dim3 block(TPB);
    dim3 grid((A + TPB - 1) / TPB, B);
    const int nblocks = grid.x * grid.y;

    if (M == 32 && C == 20)
        fl_kernel<32, 20><<<grid, block>>>(cls, reg, anc, ann, out, A, C, M, B, nblocks);
    else
        fl_kernel<0, 0><<<grid, block>>>(cls, reg, anc, ann, out, A, C, M, B, nblocks);
}